// round 17
// baseline (speedup 1.0000x reference)
#include <cuda_runtime.h>

#define B_DIM 128
#define N_DIM 8192
#define HW    49
#define ROWQ  13               // float4 quads per row window (52 floats)
#define PASS_ROWS 32
#define PASS_QUADS (PASS_ROWS * ROWQ)   // 416 quads staged per pass (6656 B)
#define ROW_STRIDE_Q4 100352   // 8192*49/4 : float4 stride between rows of x

__device__ __forceinline__ float ex2f(float x) {
    float y; asm("ex2.approx.ftz.f32 %0, %1;" : "=f"(y) : "f"(x)); return y;
}

// Exact-range scalar exp2 on the FMA pipe (R4-verified math): magic-constant
// round-to-int capture, deg-4 Taylor on frac in [-0.5,0.5] (rel err <= 4.2e-5),
// exponent applied by exact integer bit-add. Input t <= 0, clamped at -120.
__device__ __forceinline__ float poly_ex2(float t) {
    const float MAG = 12582912.0f;            // 1.5 * 2^23
    float tt = fmaxf(t, -120.0f);             // FMNMX (alu)
    float r  = tt + MAG;                      // round-to-nearest-int capture
    float fi = r - MAG;                       // integer part (exact)
    float f  = tt - fi;                       // frac in [-0.5, 0.5] (exact)
    float p  = fmaf(0.009618129f, f, 0.055504109f);   // FFMA-imm (rt 1)
    p = fmaf(p, f, 0.240226507f);
    p = fmaf(p, f, 0.693147181f);
    p = fmaf(p, f, 1.0f);
    return __int_as_float(__float_as_int(p) + (__float_as_int(r) << 23));
}

__global__ __launch_bounds__(128, 16) void rsca_kernel(
    const float* __restrict__ x, const float* __restrict__ y,
    const float* __restrict__ swq, const float* __restrict__ swk,
    const float* __restrict__ swv, const float* __restrict__ sbq,
    const float* __restrict__ sbk, const float* __restrict__ sbv,
    const float* __restrict__ swo, const float* __restrict__ sbo,
    float* __restrict__ out)
{
    const int n = blockIdx.x;
    const int i = threadIdx.x;

    __shared__ float4 xs[PASS_QUADS];  // 6656 B : 32-row staging window
    __shared__ float4 kv[B_DIM];       // 2 KB   : {kx, ky, vx, vy}
    __shared__ float4 wred[4];

    const float wq = *swq, wk = *swk, wv = *swv;
    const float bq = *sbq, bk = *sbk, bv = *sbv;
    const float wo = *swo, bo = *sbo;

    // ---- Pooling in FOUR passes of 32 rows (cheap staged, high-occ) ----
    const int a = n & 3;
    const size_t baseq = ((size_t)n * HW - a) >> 2;       // float4 offset, exact
    const float4* g4 = (const float4*)x + baseq;

    float sum = 0.f;

    #pragma unroll
    for (int pass = 0; pass < 4; ++pass) {
        #pragma unroll
        for (int t = 0; t < 4; ++t) {
            int idx = i + t * B_DIM;
            if (idx < PASS_QUADS) {
                int r = idx / ROWQ, q = idx - r * ROWQ;
                xs[idx] = g4[(size_t)(r + pass * PASS_ROWS) * ROW_STRIDE_Q4 + q];
            }
        }
        __syncthreads();

        if ((i >> 5) == pass) {           // warp `pass` reduces its own rows
            const int li = i & 31;
            float4 q0 = xs[li * ROWQ + 0];
            float4 q12 = xs[li * ROWQ + 12];
            float s0 = q0.x + q0.y, s1 = q0.z + q0.w, s2 = 0.f, s3 = 0.f;
            #pragma unroll
            for (int t = 1; t < 12; t += 2) {
                float4 u = xs[li * ROWQ + t];
                float4 w = xs[li * ROWQ + t + 1];
                s0 += u.x; s1 += u.y; s2 += u.z; s3 += u.w;
                s0 += w.x; s1 += w.y; s2 += w.z; s3 += w.w;
            }
            sum = (s0 + s1) + (s2 + s3);   // w0..w51 each exactly once
            if (a >= 1) sum -= q0.x;  else sum -= q12.y;   // w0  vs w49
            if (a >= 2) sum -= q0.y;  else sum -= q12.z;   // w1  vs w50
            if (a >= 3) sum -= q0.z;  else sum -= q12.w;   // w2  vs w51
        }
        __syncthreads();
    }

    const float ax = sum * (1.0f / 49.0f);
    const float ay = y[(size_t)i * N_DIM + (size_t)n];

    // ---- projections (k pre-scaled by log2 e) ----
    const float L2E = 1.4426950408889634f;
    const float qx = fmaf(ax, wq, bq);
    const float qy = fmaf(ay, wq, bq);
    const float kx = fmaf(ax, wk, bk) * L2E;
    const float ky = fmaf(ay, wk, bk) * L2E;
    const float vx = fmaf(ax, wv, bv);
    const float vy = fmaf(ay, wv, bv);

    kv[i] = make_float4(kx, ky, vx, vy);

    // ---- block min/max of kx, ky (analytic per-row softmax max) ----
    float kxmx = kx, kxmn = kx, kymx = ky, kymn = ky;
    #pragma unroll
    for (int off = 16; off; off >>= 1) {
        kxmx = fmaxf(kxmx, __shfl_xor_sync(0xFFFFFFFFu, kxmx, off));
        kxmn = fminf(kxmn, __shfl_xor_sync(0xFFFFFFFFu, kxmn, off));
        kymx = fmaxf(kymx, __shfl_xor_sync(0xFFFFFFFFu, kymx, off));
        kymn = fminf(kymn, __shfl_xor_sync(0xFFFFFFFFu, kymn, off));
    }
    if ((i & 31) == 0) wred[i >> 5] = make_float4(kxmx, kxmn, kymx, kymn);
    __syncthreads();
    {
        float4 r0 = wred[0], r1 = wred[1], r2 = wred[2], r3 = wred[3];
        kxmx = fmaxf(fmaxf(r0.x, r1.x), fmaxf(r2.x, r3.x));
        kxmn = fminf(fminf(r0.y, r1.y), fminf(r2.y, r3.y));
        kymx = fmaxf(fmaxf(r0.z, r1.z), fmaxf(r2.z, r3.z));
        kymn = fminf(fminf(r0.w, r1.w), fminf(r2.w, r3.w));
    }

    const float nm1 = -((qx >= 0.f) ? qx * kxmx : qx * kxmn);  // self_x : qx,kx
    const float nm2 = -((qy >= 0.f) ? qy * kymx : qy * kymn);  // self_y : qy,ky
    const float nm3 = -((qx >= 0.f) ? qx * kymx : qx * kymn);  // cross_x: qx,ky
    const float nm4 = -((qy >= 0.f) ? qy * kxmx : qy * kxmn);  // cross_y: qy,kx

    // ---- fused 4-combo attention: scalar, 4 exps/j; in 3 of 8 iterations
    // e3 is computed on the FMA pipe (poly) to rebalance MUFU vs FMA ----
    float n1 = 0.f, d1 = 0.f, n2 = 0.f, d2 = 0.f;
    float n3 = 0.f, d3 = 0.f, n4 = 0.f, d4 = 0.f;

    for (int jb = 0; jb < B_DIM; jb += 8) {
        #pragma unroll
        for (int u = 0; u < 8; ++u) {
            const float4 p = kv[jb + u];   // {kx, ky, vx, vy} broadcast LDS.128
            const float e1 = ex2f(fmaf(qx, p.x, nm1));
            const float e2 = ex2f(fmaf(qy, p.y, nm2));
            const float s3 = fmaf(qx, p.y, nm3);
            const float e3 = (u == 1 || u == 4 || u == 6) ? poly_ex2(s3) : ex2f(s3);
            const float e4 = ex2f(fmaf(qy, p.x, nm4));
            d1 += e1; n1 = fmaf(e1, p.z, n1);
            d2 += e2; n2 = fmaf(e2, p.w, n2);
            d3 += e3; n3 = fmaf(e3, p.w, n3);
            d4 += e4; n4 = fmaf(e4, p.z, n4);
        }
    }

    const float osx = __fdividef(n1, d1);
    const float osy = __fdividef(n2, d2);
    const float ocx = __fdividef(n3, d3);
    const float ocy = __fdividef(n4, d4);

    const float ox = fmaf(wo, osx + ocx, ax + 2.0f * bo);
    const float oy = fmaf(wo, osy + ocy, ay + 2.0f * bo);

    out[(size_t)i * (2 * N_DIM) + (size_t)n]         = ox;
    out[(size_t)i * (2 * N_DIM) + N_DIM + (size_t)n] = oy;
}

extern "C" void kernel_launch(void* const* d_in, const int* in_sizes, int n_in,
                              void* d_out, int out_size) {
    const float* x   = (const float*)d_in[0];
    const float* y   = (const float*)d_in[1];
    const float* swq = (const float*)d_in[2];
    const float* swk = (const float*)d_in[3];
    const float* swv = (const float*)d_in[4];
    const float* sbq = (const float*)d_in[5];
    const float* sbk = (const float*)d_in[6];
    const float* sbv = (const float*)d_in[7];
    const float* swo = (const float*)d_in[8];
    const float* sbo = (const float*)d_in[9];
    float* out = (float*)d_out;

    rsca_kernel<<<N_DIM, B_DIM>>>(x, y, swq, swk, swv, sbq, sbk, sbv, swo, sbo, out);
}